// round 1
// baseline (speedup 1.0000x reference)
#include <cuda_runtime.h>
#include <cstdint>

// Problem constants (fixed shapes for this problem instance)
#define BS 4
#define C  64
#define H  160
#define W  160
#define KK 25          // 5x5 taps
#define CH_SPLIT 2
#define CH_PER (C / CH_SPLIT)   // 32 channels per block
#define XG 8           // x-groups (of 4 px) per block  -> 32 px span
#define YB 16          // rows per block

typedef unsigned long long u64;

__device__ __forceinline__ u64 pk2(float lo, float hi) {
    u64 r; asm("mov.b64 %0, {%1, %2};" : "=l"(r) : "f"(lo), "f"(hi)); return r;
}
__device__ __forceinline__ void up2(u64 v, float &lo, float &hi) {
    asm("mov.b64 {%0, %1}, %2;" : "=f"(lo), "=f"(hi) : "l"(v));
}
__device__ __forceinline__ void fma2(u64 &acc, u64 a, u64 b) {
    // packed f32x2 FMA (Blackwell FFMA2) — 2 fp32 lanes per issue
    asm("fma.rn.f32x2 %0, %1, %2, %0;" : "+l"(acc) : "l"(a), "l"(b));
}
__device__ __forceinline__ float2 ldp(const float* p, bool pred) {
    float2 v = make_float2(0.f, 0.f);
    if (pred) v = *reinterpret_cast<const float2*>(p);
    return v;
}

__global__ void __launch_bounds__(XG * YB)
kconv_kernel(const float* __restrict__ fm, const float* __restrict__ kern,
             const int* __restrict__ dil, float* __restrict__ out)
{
    const int x0 = (blockIdx.x * XG + threadIdx.x) * 4;
    const int y  = blockIdx.y * YB + threadIdx.y;
    const int bz = blockIdx.z;
    const int b  = bz >> 1;
    const int c0 = (bz & 1) * CH_PER;
    const int d  = dil ? dil[0] : 1;

    // ---- Load this pixel-group's 25 weight quads (flipped tap order) into registers.
    // Weight for tap (i,j) at offset (y+(i-2)d, x+(j-2)d) is kernel[b, 24-(5i+j), y, x].
    u64 w01[KK], w23[KK];
    {
        const float* kb = kern + ((size_t)b * KK * H + y) * W + x0;
        #pragma unroll
        for (int t = 0; t < KK; t++) {
            const float4 wq =
                *reinterpret_cast<const float4*>(kb + (size_t)(KK - 1 - t) * H * W);
            w01[t] = pk2(wq.x, wq.y);   // weights for pixels x0, x0+1
            w23[t] = pk2(wq.z, wq.w);   // weights for pixels x0+2, x0+3
        }
    }

    if (d == 1) {
        // ---- Fast path (dilation == 1) ----
        // fm window per tap-row: x0-2 .. x0+5, loaded as 4 aligned float2s.
        // x0 is a multiple of 4, so every float2 is fully in-bounds or fully out.
        const bool pL = (x0 >= 2);
        const bool pR = (x0 + 5 < W);
        bool rv[5];
        #pragma unroll
        for (int i = 0; i < 5; i++) {
            const int yy = y + i - 2;
            rv[i] = (yy >= 0) && (yy < H);
        }

        const float* fb = fm  + ((size_t)(b * C + c0) * H + (y - 2)) * W + x0;
        float*       ob = out + ((size_t)(b * C + c0) * H +  y     ) * W + x0;

        #pragma unroll 2
        for (int c = 0; c < CH_PER; c++) {
            u64 acc01 = 0ull, acc23 = 0ull;       // (0.f, 0.f)
            const float* fc = fb + (size_t)c * H * W;
            #pragma unroll
            for (int i = 0; i < 5; i++) {
                const float* rp = fc + i * W;
                const bool r = rv[i];
                const float2 f0 = ldp(rp - 2, r && pL);
                const float2 f1 = ldp(rp,     r);
                const float2 f2 = ldp(rp + 2, r);
                const float2 f3 = ldp(rp + 4, r && pR);
                // window values w[k] = fm[x0-2+k], k = 0..7
                const u64 A0 = pk2(f0.x, f0.y);
                const u64 A2 = pk2(f1.x, f1.y);
                const u64 A4 = pk2(f2.x, f2.y);
                const u64 A6 = pk2(f3.x, f3.y);
                const u64 A1 = pk2(f0.y, f1.x);
                const u64 A3 = pk2(f1.y, f2.x);
                const u64 A5 = pk2(f2.y, f3.x);
                const int t = i * 5;
                fma2(acc01, A0, w01[t + 0]); fma2(acc23, A2, w23[t + 0]);
                fma2(acc01, A1, w01[t + 1]); fma2(acc23, A3, w23[t + 1]);
                fma2(acc01, A2, w01[t + 2]); fma2(acc23, A4, w23[t + 2]);
                fma2(acc01, A3, w01[t + 3]); fma2(acc23, A5, w23[t + 3]);
                fma2(acc01, A4, w01[t + 4]); fma2(acc23, A6, w23[t + 4]);
            }
            float4 o;
            up2(acc01, o.x, o.y);
            up2(acc23, o.z, o.w);
            *reinterpret_cast<float4*>(ob + (size_t)c * H * W) = o;
        }
    } else {
        // ---- Generic dilation path (correctness fallback; not the benched case) ----
        #pragma unroll 1
        for (int c = 0; c < CH_PER; c++) {
            float a0 = 0.f, a1 = 0.f, a2 = 0.f, a3 = 0.f;
            const float* fc = fm + (size_t)((b * C + c0 + c) * H) * W;
            #pragma unroll
            for (int i = 0; i < 5; i++) {
                const int yy = y + (i - 2) * d;
                if (yy < 0 || yy >= H) continue;
                const float* rp = fc + yy * W;
                #pragma unroll
                for (int j = 0; j < 5; j++) {
                    float wlo, whi, wl2, wh2;
                    up2(w01[i * 5 + j], wlo, whi);
                    up2(w23[i * 5 + j], wl2, wh2);
                    const int xb = x0 + (j - 2) * d;
                    a0 += wlo * ((xb     >= 0 && xb     < W) ? rp[xb    ] : 0.f);
                    a1 += whi * ((xb + 1 >= 0 && xb + 1 < W) ? rp[xb + 1] : 0.f);
                    a2 += wl2 * ((xb + 2 >= 0 && xb + 2 < W) ? rp[xb + 2] : 0.f);
                    a3 += wh2 * ((xb + 3 >= 0 && xb + 3 < W) ? rp[xb + 3] : 0.f);
                }
            }
            float* op = out + (size_t)((b * C + c0 + c) * H + y) * W + x0;
            op[0] = a0; op[1] = a1; op[2] = a2; op[3] = a3;
        }
    }
}

extern "C" void kernel_launch(void* const* d_in, const int* in_sizes, int n_in,
                              void* d_out, int out_size) {
    const float* fm   = (const float*)d_in[0];
    const float* kern = (const float*)d_in[1];
    const int*   dil  = (n_in > 2) ? (const int*)d_in[2] : nullptr;
    float*       out  = (float*)d_out;

    dim3 blk(XG, YB, 1);                        // 128 threads
    dim3 grd(W / 4 / XG, H / YB, BS * CH_SPLIT); // (5, 10, 8) = 400 blocks
    kconv_kernel<<<grd, blk>>>(fm, kern, dil, out);
}

// round 6
// speedup vs baseline: 1.0338x; 1.0338x over previous
#include <cuda_runtime.h>
#include <cstdint>

// Problem constants (fixed shapes for this problem instance)
#define BS 4
#define C  64
#define H  160
#define W  160
#define KK 25          // 5x5 taps
#define CH_SPLIT 2
#define CH_PER (C / CH_SPLIT)   // 32 channels per block
#define XG 16          // x-groups (of 2 px) per block -> 32 px span
#define YB 8           // rows per block

typedef unsigned long long u64;

__device__ __forceinline__ u64 pk2(float lo, float hi) {
    u64 r; asm("mov.b64 %0, {%1, %2};" : "=l"(r) : "f"(lo), "f"(hi)); return r;
}
__device__ __forceinline__ void up2(u64 v, float &lo, float &hi) {
    asm("mov.b64 {%0, %1}, %2;" : "=f"(lo), "=f"(hi) : "l"(v));
}
__device__ __forceinline__ void fma2(u64 &acc, u64 a, u64 b) {
    // packed f32x2 FMA (Blackwell FFMA2) — 2 fp32 lanes per issue
    asm("fma.rn.f32x2 %0, %1, %2, %0;" : "+l"(acc) : "l"(a), "l"(b));
}
__device__ __forceinline__ float2 ldp(const float* p, bool pred) {
    float2 v = make_float2(0.f, 0.f);
    if (pred) v = *reinterpret_cast<const float2*>(p);
    return v;
}

__global__ void __launch_bounds__(XG * YB, 4)
kconv_kernel(const float* __restrict__ fm, const float* __restrict__ kern,
             const int* __restrict__ dil, float* __restrict__ out)
{
    const int x0 = (blockIdx.x * XG + threadIdx.x) * 2;
    const int y  = blockIdx.y * YB + threadIdx.y;
    const int bz = blockIdx.z;
    const int b  = bz >> 1;
    const int c0 = (bz & 1) * CH_PER;
    const int d  = dil ? dil[0] : 1;

    // ---- Load this pixel-pair's 25 weight pairs (flipped tap order) into registers.
    // Weight for tap (i,j) at offset (y+(i-2)d, x+(j-2)d) is kernel[b, 24-(5i+j), y, x].
    u64 wt[KK];
    {
        const float* kb = kern + ((size_t)b * KK * H + y) * W + x0;
        #pragma unroll
        for (int t = 0; t < KK; t++) {
            const float2 wq =
                *reinterpret_cast<const float2*>(kb + (size_t)(KK - 1 - t) * H * W);
            wt[t] = pk2(wq.x, wq.y);   // weights for pixels x0, x0+1
        }
    }

    if (d == 1) {
        // ---- Fast path (dilation == 1) ----
        // fm window per tap-row: x0-2 .. x0+3, loaded as 3 aligned float2s.
        // x0 is even, so each float2 is fully in-bounds or fully out.
        const bool pL = (x0 >= 2);
        const bool pR = (x0 + 2 < W);
        bool rv[5];
        #pragma unroll
        for (int i = 0; i < 5; i++) {
            const int yy = y + i - 2;
            rv[i] = (yy >= 0) && (yy < H);
        }

        const float* fb = fm  + ((size_t)(b * C + c0) * H + (y - 2)) * W + x0;
        float*       ob = out + ((size_t)(b * C + c0) * H +  y     ) * W + x0;

        #pragma unroll 2
        for (int c = 0; c < CH_PER; c++) {
            u64 acc = 0ull;                        // (0.f, 0.f)
            const float* fc = fb + (size_t)c * H * W;
            #pragma unroll
            for (int i = 0; i < 5; i++) {
                const float* rp = fc + i * W;
                const bool r = rv[i];
                const float2 f0 = ldp(rp - 2, r && pL);   // w0 w1  (x0-2, x0-1)
                const float2 f1 = ldp(rp,     r);         // w2 w3  (x0,   x0+1)
                const float2 f2 = ldp(rp + 2, r && pR);   // w4 w5  (x0+2, x0+3)
                const u64 A0 = pk2(f0.x, f0.y);
                const u64 A2 = pk2(f1.x, f1.y);
                const u64 A4 = pk2(f2.x, f2.y);
                const u64 A1 = pk2(f0.y, f1.x);
                const u64 A3 = pk2(f1.y, f2.x);
                const int t = i * 5;
                fma2(acc, A0, wt[t + 0]);
                fma2(acc, A1, wt[t + 1]);
                fma2(acc, A2, wt[t + 2]);
                fma2(acc, A3, wt[t + 3]);
                fma2(acc, A4, wt[t + 4]);
            }
            float2 o;
            up2(acc, o.x, o.y);
            *reinterpret_cast<float2*>(ob + (size_t)c * H * W) = o;
        }
    } else {
        // ---- Generic dilation path (correctness fallback; not the benched case) ----
        #pragma unroll 1
        for (int c = 0; c < CH_PER; c++) {
            float a0 = 0.f, a1 = 0.f;
            const float* fc = fm + (size_t)((b * C + c0 + c) * H) * W;
            #pragma unroll
            for (int i = 0; i < 5; i++) {
                const int yy = y + (i - 2) * d;
                if (yy < 0 || yy >= H) continue;
                const float* rp = fc + yy * W;
                #pragma unroll
                for (int j = 0; j < 5; j++) {
                    float wlo, whi;
                    up2(wt[i * 5 + j], wlo, whi);
                    const int xb = x0 + (j - 2) * d;
                    a0 += wlo * ((xb     >= 0 && xb     < W) ? rp[xb    ] : 0.f);
                    a1 += whi * ((xb + 1 >= 0 && xb + 1 < W) ? rp[xb + 1] : 0.f);
                }
            }
            float* op = out + (size_t)((b * C + c0 + c) * H + y) * W + x0;
            op[0] = a0; op[1] = a1;
        }
    }
}

extern "C" void kernel_launch(void* const* d_in, const int* in_sizes, int n_in,
                              void* d_out, int out_size) {
    const float* fm   = (const float*)d_in[0];
    const float* kern = (const float*)d_in[1];
    const int*   dil  = (n_in > 2) ? (const int*)d_in[2] : nullptr;
    float*       out  = (float*)d_out;

    dim3 blk(XG, YB, 1);                          // 128 threads
    dim3 grd(W / 2 / XG, H / YB, BS * CH_SPLIT);  // (5, 20, 8) = 800 blocks
    kconv_kernel<<<grd, blk>>>(fm, kern, dil, out);
}

// round 7
// speedup vs baseline: 1.7671x; 1.7092x over previous
#include <cuda_runtime.h>
#include <cstdint>

// Problem constants (fixed shapes for this problem instance)
#define BS 4
#define C  64
#define H  160
#define W  160
#define KK 25          // 5x5 taps
#define CH_SPLIT 2
#define CH_PER (C / CH_SPLIT)   // 32 channels per block
#define XG 16          // x-groups (of 2 px) per block -> 32 px span
#define YB 8           // rows per block

typedef unsigned long long u64;

__device__ __forceinline__ u64 pk2(float lo, float hi) {
    u64 r; asm("mov.b64 %0, {%1, %2};" : "=l"(r) : "f"(lo), "f"(hi)); return r;
}
__device__ __forceinline__ void up2(u64 v, float &lo, float &hi) {
    asm("mov.b64 {%0, %1}, %2;" : "=f"(lo), "=f"(hi) : "l"(v));
}
__device__ __forceinline__ void fma2(u64 &acc, u64 a, u64 b) {
    // packed f32x2 FMA (Blackwell FFMA2) — 2 fp32 lanes per issue
    asm("fma.rn.f32x2 %0, %1, %2, %0;" : "+l"(acc) : "l"(a), "l"(b));
}

__global__ void __launch_bounds__(XG * YB, 4)
kconv_kernel(const float* __restrict__ fm, const float* __restrict__ kern,
             const int* __restrict__ dil, float* __restrict__ out)
{
    const int x0 = (blockIdx.x * XG + threadIdx.x) * 2;
    const int y  = blockIdx.y * YB + threadIdx.y;
    const int bz = blockIdx.z;
    const int b  = bz >> 1;
    const int c0 = (bz & 1) * CH_PER;
    const int d  = dil ? dil[0] : 1;

    // ---- Load this pixel-pair's 25 weight pairs (flipped tap order) into registers.
    // Weight for tap (i,j) at offset (y+(i-2)d, x+(j-2)d) is kernel[b, 24-(5i+j), y, x].
    u64 wt[KK];
    {
        const float* kb = kern + ((size_t)b * KK * H + y) * W + x0;
        #pragma unroll
        for (int t = 0; t < KK; t++) {
            const float2 wq =
                *reinterpret_cast<const float2*>(kb + (size_t)(KK - 1 - t) * H * W);
            wt[t] = pk2(wq.x, wq.y);   // weights for pixels x0, x0+1
        }
    }

    if (d == 1) {
        // ---- Fast path (dilation == 1) ----
        // Boundary handling is folded into the weights ONCE per thread:
        // any tap whose source pixel is out-of-bounds gets weight 0, and the
        // corresponding load address is clamped into bounds (garbage * 0 = 0).
        // The channel loop then contains NO predication and NO branches.
        #pragma unroll
        for (int i = 0; i < 5; i++) {
            const int yy = y + i - 2;
            const bool rok = (yy >= 0) && (yy < H);
            #pragma unroll
            for (int j = 0; j < 5; j++) {
                float lo, hi;
                up2(wt[i * 5 + j], lo, hi);
                const int xe0 = x0 + j - 2;       // pixel x0 source column
                const int xe1 = x0 + 1 + j - 2;   // pixel x0+1 source column
                if (!rok || xe0 < 0 || xe0 >= W) lo = 0.f;
                if (!rok || xe1 < 0 || xe1 >= W) hi = 0.f;
                wt[i * 5 + j] = pk2(lo, hi);
            }
        }

        // Clamped row offsets (always a valid row; weight=0 kills wrong values).
        int ro[5];
        #pragma unroll
        for (int i = 0; i < 5; i++) {
            int yy = y + i - 2;
            yy = yy < 0 ? 0 : (yy >= H ? H - 1 : yy);
            ro[i] = yy * W;
        }
        // Clamped x offsets for the three aligned float2 window loads.
        const int xoL = (x0 >= 2)     ? x0 - 2 : 0;        // stays 8B-aligned
        const int xoR = (x0 + 2 < W)  ? x0 + 2 : W - 2;

        const float* fb = fm  + (size_t)(b * C + c0) * H * W;
        float*       ob = out + ((size_t)(b * C + c0) * H + y) * W + x0;

        #pragma unroll 2
        for (int c = 0; c < CH_PER; c++) {
            u64 acc = 0ull;                        // (0.f, 0.f)
            const float* fc = fb + (size_t)c * H * W;
            #pragma unroll
            for (int i = 0; i < 5; i++) {
                const float* rp = fc + ro[i];
                // unconditional, aligned 8B loads
                const float2 f0 = *reinterpret_cast<const float2*>(rp + xoL);
                const float2 f1 = *reinterpret_cast<const float2*>(rp + x0);
                const float2 f2 = *reinterpret_cast<const float2*>(rp + xoR);
                const u64 A0 = pk2(f0.x, f0.y);
                const u64 A2 = pk2(f1.x, f1.y);
                const u64 A4 = pk2(f2.x, f2.y);
                const u64 A1 = pk2(f0.y, f1.x);
                const u64 A3 = pk2(f1.y, f2.x);
                const int t = i * 5;
                fma2(acc, A0, wt[t + 0]);
                fma2(acc, A1, wt[t + 1]);
                fma2(acc, A2, wt[t + 2]);
                fma2(acc, A3, wt[t + 3]);
                fma2(acc, A4, wt[t + 4]);
            }
            float2 o;
            up2(acc, o.x, o.y);
            *reinterpret_cast<float2*>(ob + (size_t)c * H * W) = o;
        }
    } else {
        // ---- Generic dilation path (correctness fallback; not the benched case) ----
        #pragma unroll 1
        for (int c = 0; c < CH_PER; c++) {
            float a0 = 0.f, a1 = 0.f;
            const float* fc = fm + (size_t)((b * C + c0 + c) * H) * W;
            #pragma unroll
            for (int i = 0; i < 5; i++) {
                const int yy = y + (i - 2) * d;
                if (yy < 0 || yy >= H) continue;
                const float* rp = fc + yy * W;
                #pragma unroll
                for (int j = 0; j < 5; j++) {
                    float wlo, whi;
                    up2(wt[i * 5 + j], wlo, whi);
                    const int xb = x0 + (j - 2) * d;
                    a0 += wlo * ((xb     >= 0 && xb     < W) ? rp[xb    ] : 0.f);
                    a1 += whi * ((xb + 1 >= 0 && xb + 1 < W) ? rp[xb + 1] : 0.f);
                }
            }
            float* op = out + (size_t)((b * C + c0 + c) * H + y) * W + x0;
            op[0] = a0; op[1] = a1;
        }
    }
}

extern "C" void kernel_launch(void* const* d_in, const int* in_sizes, int n_in,
                              void* d_out, int out_size) {
    const float* fm   = (const float*)d_in[0];
    const float* kern = (const float*)d_in[1];
    const int*   dil  = (n_in > 2) ? (const int*)d_in[2] : nullptr;
    float*       out  = (float*)d_out;

    dim3 blk(XG, YB, 1);                          // 128 threads
    dim3 grd(W / 2 / XG, H / YB, BS * CH_SPLIT);  // (5, 20, 8) = 800 blocks
    kconv_kernel<<<grd, blk>>>(fm, kern, dil, out);
}

// round 8
// speedup vs baseline: 2.5731x; 1.4561x over previous
#include <cuda_runtime.h>
#include <cstdint>

// Problem constants (fixed shapes for this problem instance)
#define BS 4
#define C  64
#define H  160
#define W  160
#define KK 25          // 5x5 taps
#define CH_SPLIT 2
#define CH_PER (C / CH_SPLIT)   // 32 channels per block
#define XQ 8           // x-quads (of 4 px) per block -> 32 px span
#define YB 16          // rows per block

typedef unsigned long long u64;

__device__ __forceinline__ u64 pk2(float lo, float hi) {
    u64 r; asm("mov.b64 %0, {%1, %2};" : "=l"(r) : "f"(lo), "f"(hi)); return r;
}
__device__ __forceinline__ void up2(u64 v, float &lo, float &hi) {
    asm("mov.b64 {%0, %1}, %2;" : "=f"(lo), "=f"(hi) : "l"(v));
}
__device__ __forceinline__ void fma2(u64 &acc, u64 a, u64 b) {
    // packed f32x2 FMA (Blackwell FFMA2) — 2 fp32 lanes per issue
    asm("fma.rn.f32x2 %0, %1, %2, %0;" : "+l"(acc) : "l"(a), "l"(b));
}
__device__ __forceinline__ u64 add2(u64 a, u64 b) {
    u64 r; asm("add.rn.f32x2 %0, %1, %2;" : "=l"(r) : "l"(a), "l"(b)); return r;
}

__global__ void __launch_bounds__(XQ * YB, 3)
kconv_kernel(const float* __restrict__ fm, const float* __restrict__ kern,
             const int* __restrict__ dil, float* __restrict__ out)
{
    const int x0 = (blockIdx.x * XQ + threadIdx.x) * 4;
    const int y  = blockIdx.y * YB + threadIdx.y;
    const int bz = blockIdx.z;
    const int b  = bz >> 1;
    const int c0 = (bz & 1) * CH_PER;
    const int d  = dil ? dil[0] : 1;

    // ---- Load this pixel-quad's 25 weight quads (flipped tap order) into registers.
    // Weight for tap (i,j) at offset (y+(i-2)d, x+(j-2)d) is kernel[b, 24-(5i+j), y, x].
    u64 w01[KK], w23[KK];
    {
        const float* kb = kern + ((size_t)b * KK * H + y) * W + x0;
        #pragma unroll
        for (int t = 0; t < KK; t++) {
            const float4 wq =
                *reinterpret_cast<const float4*>(kb + (size_t)(KK - 1 - t) * H * W);
            w01[t] = pk2(wq.x, wq.y);   // weights for pixels x0, x0+1
            w23[t] = pk2(wq.z, wq.w);   // weights for pixels x0+2, x0+3
        }
    }

    if (d == 1) {
        // ---- Fast path (dilation == 1), fully branchless inner loop ----
        // Boundary handling folded into the weights ONCE per thread: any tap whose
        // source pixel is out-of-bounds gets weight 0; load addresses are clamped
        // to valid memory (garbage * 0 = 0).
        #pragma unroll
        for (int i = 0; i < 5; i++) {
            const int yy = y + i - 2;
            const bool rok = (yy >= 0) && (yy < H);
            #pragma unroll
            for (int j = 0; j < 5; j++) {
                float a0, a1, a2, a3;
                up2(w01[i * 5 + j], a0, a1);
                up2(w23[i * 5 + j], a2, a3);
                if (!rok || x0 + 0 + j - 2 < 0 || x0 + 0 + j - 2 >= W) a0 = 0.f;
                if (!rok || x0 + 1 + j - 2 < 0 || x0 + 1 + j - 2 >= W) a1 = 0.f;
                if (!rok || x0 + 2 + j - 2 < 0 || x0 + 2 + j - 2 >= W) a2 = 0.f;
                if (!rok || x0 + 3 + j - 2 < 0 || x0 + 3 + j - 2 >= W) a3 = 0.f;
                w01[i * 5 + j] = pk2(a0, a1);
                w23[i * 5 + j] = pk2(a2, a3);
            }
        }

        // Clamped row offsets (always a valid row; weight=0 kills wrong values).
        int ro[5];
        #pragma unroll
        for (int i = 0; i < 5; i++) {
            int yy = y + i - 2;
            yy = yy < 0 ? 0 : (yy >= H ? H - 1 : yy);
            ro[i] = yy * W;
        }
        // Window v0..v9 = fm[x0-4 .. x0+5]:
        //   LDG.128 @ xL  -> v0..v3   (xL = x0-4, clamped to 0 when x0==0; 16B aligned)
        //   LDG.128 @ x0  -> v4..v7   (always in-bounds, 16B aligned)
        //   LDG.64  @ xR  -> v8,v9    (xR = x0+4, clamped when x0+5 >= W; 8B aligned)
        const int xL = (x0 >= 4)     ? x0 - 4 : 0;
        const int xR = (x0 + 5 < W)  ? x0 + 4 : x0;

        const float* fb = fm  + (size_t)(b * C + c0) * H * W;
        float*       ob = out + ((size_t)(b * C + c0) * H + y) * W + x0;

        #pragma unroll 2
        for (int c = 0; c < CH_PER; c++) {
            // 4 independent accumulation chains (even/odd taps x pixel-pair)
            u64 accA = 0ull, accB = 0ull, accC = 0ull, accD = 0ull;
            const float* fc = fb + (size_t)c * H * W;
            #pragma unroll
            for (int i = 0; i < 5; i++) {
                const float* rp = fc + ro[i];
                const float4 fa = *reinterpret_cast<const float4*>(rp + xL); // v0..v3
                const float4 fb4 = *reinterpret_cast<const float4*>(rp + x0); // v4..v7
                const float2 fcx = *reinterpret_cast<const float2*>(rp + xR); // v8,v9
                const u64 P23 = pk2(fa.z,  fa.w);
                const u64 P45 = pk2(fb4.x, fb4.y);
                const u64 P67 = pk2(fb4.z, fb4.w);
                const u64 P89 = pk2(fcx.x, fcx.y);
                const u64 P34 = pk2(fa.w,  fb4.x);
                const u64 P56 = pk2(fb4.y, fb4.z);
                const u64 P78 = pk2(fb4.w, fcx.x);
                const int t = i * 5;
                // pixel pair (x0, x0+1): taps read v[2+j], v[3+j]
                fma2(accA, P23, w01[t + 0]);
                fma2(accB, P34, w01[t + 1]);
                fma2(accA, P45, w01[t + 2]);
                fma2(accB, P56, w01[t + 3]);
                fma2(accA, P67, w01[t + 4]);
                // pixel pair (x0+2, x0+3): taps read v[4+j], v[5+j]
                fma2(accC, P45, w23[t + 0]);
                fma2(accD, P56, w23[t + 1]);
                fma2(accC, P67, w23[t + 2]);
                fma2(accD, P78, w23[t + 3]);
                fma2(accC, P89, w23[t + 4]);
            }
            const u64 s01 = add2(accA, accB);
            const u64 s23 = add2(accC, accD);
            float4 o;
            up2(s01, o.x, o.y);
            up2(s23, o.z, o.w);
            *reinterpret_cast<float4*>(ob + (size_t)c * H * W) = o;
        }
    } else {
        // ---- Generic dilation path (correctness fallback; not the benched case) ----
        #pragma unroll 1
        for (int c = 0; c < CH_PER; c++) {
            float a0 = 0.f, a1 = 0.f, a2 = 0.f, a3 = 0.f;
            const float* fc = fm + (size_t)((b * C + c0 + c) * H) * W;
            #pragma unroll
            for (int i = 0; i < 5; i++) {
                const int yy = y + (i - 2) * d;
                if (yy < 0 || yy >= H) continue;
                const float* rp = fc + yy * W;
                #pragma unroll
                for (int j = 0; j < 5; j++) {
                    float wlo, whi, wl2, wh2;
                    up2(w01[i * 5 + j], wlo, whi);
                    up2(w23[i * 5 + j], wl2, wh2);
                    const int xb = x0 + (j - 2) * d;
                    a0 += wlo * ((xb     >= 0 && xb     < W) ? rp[xb    ] : 0.f);
                    a1 += whi * ((xb + 1 >= 0 && xb + 1 < W) ? rp[xb + 1] : 0.f);
                    a2 += wl2 * ((xb + 2 >= 0 && xb + 2 < W) ? rp[xb + 2] : 0.f);
                    a3 += wh2 * ((xb + 3 >= 0 && xb + 3 < W) ? rp[xb + 3] : 0.f);
                }
            }
            float* op = out + (size_t)((b * C + c0 + c) * H + y) * W + x0;
            op[0] = a0; op[1] = a1; op[2] = a2; op[3] = a3;
        }
    }
}

extern "C" void kernel_launch(void* const* d_in, const int* in_sizes, int n_in,
                              void* d_out, int out_size) {
    const float* fm   = (const float*)d_in[0];
    const float* kern = (const float*)d_in[1];
    const int*   dil  = (n_in > 2) ? (const int*)d_in[2] : nullptr;
    float*       out  = (float*)d_out;

    dim3 blk(XQ, YB, 1);                          // 128 threads
    dim3 grd(W / 4 / XQ, H / YB, BS * CH_SPLIT);  // (5, 10, 8) = 400 blocks
    kconv_kernel<<<grd, blk>>>(fm, kern, dil, out);
}

// round 11
// speedup vs baseline: 3.0556x; 1.1875x over previous
#include <cuda_runtime.h>
#include <cstdint>

// Problem constants (fixed shapes for this problem instance)
#define BS 4
#define C  64
#define H  160
#define W  160
#define HW (H * W)
#define KK 25          // 5x5 taps
#define CH_SPLIT 2
#define CH_PER (C / CH_SPLIT)   // 32 channels per block
#define XQ 8           // x-quads (of 4 px) per block -> 32 px span
#define YB 16          // rows per block (4 warps x 4 rows)
#define NSTG 3         // cp.async pipeline depth
#define SROW 40        // staged floats per row (x window: 32 + 8 halo)
#define SROWB (SROW * 4)      // 160 B
#define STAGEB (8 * SROWB)    // 1280 B per stage (8 rows)

typedef unsigned long long u64;

__device__ __forceinline__ u64 pk2(float lo, float hi) {
    u64 r; asm("mov.b64 %0, {%1, %2};" : "=l"(r) : "f"(lo), "f"(hi)); return r;
}
__device__ __forceinline__ void up2(u64 v, float &lo, float &hi) {
    asm("mov.b64 {%0, %1}, %2;" : "=f"(lo), "=f"(hi) : "l"(v));
}
__device__ __forceinline__ void fma2(u64 &acc, u64 a, u64 b) {
    asm("fma.rn.f32x2 %0, %1, %2, %0;" : "+l"(acc) : "l"(a), "l"(b));
}
__device__ __forceinline__ u64 add2(u64 a, u64 b) {
    u64 r; asm("add.rn.f32x2 %0, %1, %2;" : "=l"(r) : "l"(a), "l"(b)); return r;
}
__device__ __forceinline__ void cpa16(uint32_t s, const float* g) {
    asm volatile("cp.async.cg.shared.global [%0], [%1], 16;" :: "r"(s), "l"(g));
}
__device__ __forceinline__ float4 lds128(uint32_t a) {
    float4 v;
    asm("ld.shared.v4.f32 {%0,%1,%2,%3}, [%4];"
        : "=f"(v.x), "=f"(v.y), "=f"(v.z), "=f"(v.w) : "r"(a));
    return v;
}
__device__ __forceinline__ float2 lds64(uint32_t a) {
    float2 v;
    asm("ld.shared.v2.f32 {%0,%1}, [%2];" : "=f"(v.x), "=f"(v.y) : "r"(a));
    return v;
}
__device__ __forceinline__ int iclamp(int v, int lo, int hi) {
    return v < lo ? lo : (v > hi ? hi : v);
}

__global__ void __launch_bounds__(XQ * YB, 3)
kconv_kernel(const float* __restrict__ fm, const float* __restrict__ kern,
             const int* __restrict__ dil, float* __restrict__ out)
{
    // 4 warps x 3 stages x 8 rows x 40 floats = 15360 B
    __shared__ __align__(16) float sbuf[4 * NSTG * 8 * SROW];

    const int tx = threadIdx.x;
    const int ty = threadIdx.y;
    const int x0 = (blockIdx.x * XQ + tx) * 4;
    const int y  = blockIdx.y * YB + ty;
    const int bz = blockIdx.z;
    const int b  = bz >> 1;
    const int c0 = (bz & 1) * CH_PER;
    const int d  = dil ? dil[0] : 1;

    // ---- Load this pixel-quad's 25 weight quads (flipped tap order) into registers.
    u64 w01[KK], w23[KK];
    {
        const float* kb = kern + ((size_t)b * KK * H + y) * W + x0;
        #pragma unroll
        for (int t = 0; t < KK; t++) {
            const float4 wq =
                *reinterpret_cast<const float4*>(kb + (size_t)(KK - 1 - t) * H * W);
            w01[t] = pk2(wq.x, wq.y);
            w23[t] = pk2(wq.z, wq.w);
        }
    }

    if (d == 1) {
        // ---- Fold boundary handling into the weights ONCE per thread. ----
        #pragma unroll
        for (int i = 0; i < 5; i++) {
            const int yy = y + i - 2;
            const bool rok = (yy >= 0) && (yy < H);
            #pragma unroll
            for (int j = 0; j < 5; j++) {
                float a0, a1, a2, a3;
                up2(w01[i * 5 + j], a0, a1);
                up2(w23[i * 5 + j], a2, a3);
                if (!rok || x0 + 0 + j - 2 < 0 || x0 + 0 + j - 2 >= W) a0 = 0.f;
                if (!rok || x0 + 1 + j - 2 < 0 || x0 + 1 + j - 2 >= W) a1 = 0.f;
                if (!rok || x0 + 2 + j - 2 < 0 || x0 + 2 + j - 2 >= W) a2 = 0.f;
                if (!rok || x0 + 3 + j - 2 < 0 || x0 + 3 + j - 2 >= W) a3 = 0.f;
                w01[i * 5 + j] = pk2(a0, a1);
                w23[i * 5 + j] = pk2(a2, a3);
            }
        }

        // ---- Per-warp cp.async staging setup. ----
        // Warp w covers output rows yw0..yw0+3, x span xb..xb+31.
        // Staged region per channel: rows yw0-2..yw0+5 (clamped), cols xb-4..xb+35
        // (clamped, 16B granules). Out-of-bounds taps have zero weights.
        const int lane = tx + (ty & 3) * 8;    // == tid % 32
        const int w    = ty >> 2;
        const int tyw  = ty & 3;
        const int xb   = blockIdx.x * 32;
        const int yw0  = blockIdx.y * YB + w * 4;

        const uint32_t sbase =
            (uint32_t)__cvta_generic_to_shared(sbuf) + (uint32_t)(w * NSTG * STAGEB);

        // 80 float4 slots (8 rows x 10 quads); lane handles slots lane, lane+32, lane+64.
        int gof[3]; uint32_t sof[3];
        #pragma unroll
        for (int k = 0; k < 3; k++) {
            const int slot = lane + 32 * k;
            const int r = (slot < 80) ? slot / 10 : 0;
            const int q = (slot < 80) ? slot % 10 : 0;
            const int rg = iclamp(yw0 - 2 + r, 0, H - 1);
            const int cg = iclamp(xb - 4 + q * 4, 0, W - 4);
            gof[k] = rg * W + cg;
            sof[k] = sbase + (uint32_t)(r * SROWB + q * 16);
        }
        const bool have3 = (lane < 16);

        const float* fb = fm  + (size_t)(b * C + c0) * HW;
        float*       ob = out + ((size_t)(b * C + c0) * H + y) * W + x0;

        // Prologue: prefetch channels 0..NSTG-1.
        #pragma unroll
        for (int p = 0; p < NSTG; p++) {
            const float* fc = fb + (size_t)p * HW;
            const uint32_t so = (uint32_t)(p * STAGEB);
            cpa16(sof[0] + so, fc + gof[0]);
            cpa16(sof[1] + so, fc + gof[1]);
            if (have3) cpa16(sof[2] + so, fc + gof[2]);
            asm volatile("cp.async.commit_group;");
        }

        const uint32_t lbase = sbase + (uint32_t)(tyw * SROWB + tx * 16);
        int s = 0;

        #pragma unroll 1
        for (int c = 0; c < CH_PER; c++) {
            asm volatile("cp.async.wait_group 2;");
            __syncwarp();

            const uint32_t lb = lbase + (uint32_t)(s * STAGEB);
            u64 accA = 0ull, accB = 0ull, accC = 0ull, accD = 0ull;
            #pragma unroll
            for (int i = 0; i < 5; i++) {
                const uint32_t ra = lb + (uint32_t)(i * SROWB);
                // window values v_k = fm[x0-4+k]; smem col k at byte tx*16 + k*4.
                const float2 f23 = lds64 (ra + 8);    // v2, v3
                const float4 f47 = lds128(ra + 16);   // v4..v7
                const float2 f89 = lds64 (ra + 32);   // v8, v9
                const u64 P23 = pk2(f23.x, f23.y);
                const u64 P45 = pk2(f47.x, f47.y);
                const u64 P67 = pk2(f47.z, f47.w);
                const u64 P89 = pk2(f89.x, f89.y);
                const u64 P34 = pk2(f23.y, f47.x);
                const u64 P56 = pk2(f47.y, f47.z);
                const u64 P78 = pk2(f47.w, f89.x);
                const int t = i * 5;
                fma2(accA, P23, w01[t + 0]);
                fma2(accB, P34, w01[t + 1]);
                fma2(accA, P45, w01[t + 2]);
                fma2(accB, P56, w01[t + 3]);
                fma2(accA, P67, w01[t + 4]);
                fma2(accC, P45, w23[t + 0]);
                fma2(accD, P56, w23[t + 1]);
                fma2(accC, P67, w23[t + 2]);
                fma2(accD, P78, w23[t + 3]);
                fma2(accC, P89, w23[t + 4]);
            }
            const u64 s01 = add2(accA, accB);
            const u64 s23 = add2(accC, accD);
            float4 o;
            up2(s01, o.x, o.y);
            up2(s23, o.z, o.w);
            *reinterpret_cast<float4*>(ob) = o;
            ob += HW;

            // Prefetch channel c+NSTG into the stage just consumed.
            // Safe WAR: in-order warp issue means the FMAs consuming this stage's
            // LDS data issued (operands ready) before these LDGSTS issue.
            if (c + NSTG < CH_PER) {
                const float* fc = fb + (size_t)(c + NSTG) * HW;
                const uint32_t so = (uint32_t)(s * STAGEB);
                cpa16(sof[0] + so, fc + gof[0]);
                cpa16(sof[1] + so, fc + gof[1]);
                if (have3) cpa16(sof[2] + so, fc + gof[2]);
            }
            asm volatile("cp.async.commit_group;");   // empty group ok near the tail

            s = (s == NSTG - 1) ? 0 : s + 1;
        }
    } else {
        // ---- Generic dilation path (correctness fallback; not the benched case) ----
        #pragma unroll 1
        for (int c = 0; c < CH_PER; c++) {
            float a0 = 0.f, a1 = 0.f, a2 = 0.f, a3 = 0.f;
            const float* fc = fm + (size_t)((b * C + c0 + c) * H) * W;
            #pragma unroll
            for (int i = 0; i < 5; i++) {
                const int yy = y + (i - 2) * d;
                if (yy < 0 || yy >= H) continue;
                const float* rp = fc + yy * W;
                #pragma unroll
                for (int j = 0; j < 5; j++) {
                    float wlo, whi, wl2, wh2;
                    up2(w01[i * 5 + j], wlo, whi);
                    up2(w23[i * 5 + j], wl2, wh2);
                    const int xb2 = x0 + (j - 2) * d;
                    a0 += wlo * ((xb2     >= 0 && xb2     < W) ? rp[xb2    ] : 0.f);
                    a1 += whi * ((xb2 + 1 >= 0 && xb2 + 1 < W) ? rp[xb2 + 1] : 0.f);
                    a2 += wl2 * ((xb2 + 2 >= 0 && xb2 + 2 < W) ? rp[xb2 + 2] : 0.f);
                    a3 += wh2 * ((xb2 + 3 >= 0 && xb2 + 3 < W) ? rp[xb2 + 3] : 0.f);
                }
            }
            float* op = out + (size_t)((b * C + c0 + c) * H + y) * W + x0;
            op[0] = a0; op[1] = a1; op[2] = a2; op[3] = a3;
        }
    }
}

extern "C" void kernel_launch(void* const* d_in, const int* in_sizes, int n_in,
                              void* d_out, int out_size) {
    const float* fm   = (const float*)d_in[0];
    const float* kern = (const float*)d_in[1];
    const int*   dil  = (n_in > 2) ? (const int*)d_in[2] : nullptr;
    float*       out  = (float*)d_out;

    dim3 blk(XQ, YB, 1);                          // 128 threads, 4 warps
    dim3 grd(W / 4 / XQ, H / YB, BS * CH_SPLIT);  // (5, 10, 8) = 400 blocks
    kconv_kernel<<<grd, blk>>>(fm, kern, dil, out);
}